// round 5
// baseline (speedup 1.0000x reference)
#include <cuda_runtime.h>
#include <cuda_fp16.h>
#include <cstdint>

#define TT   4096
#define DD   2048
#define FF   2048
#define EE   8
#define CAP  4096

// ---------------- storage: fp16 activations (hi/lo) + fp16 weights ----------
__device__ __half g_x_hi[(size_t)TT * DD];
__device__ __half g_x_lo[(size_t)TT * DD];
__device__ __half g_sw13[(size_t)2 * FF * DD];
__device__ __half g_sw2[(size_t)DD * FF];
__device__ __half g_rw13[(size_t)EE * 2 * FF * DD];
__device__ __half g_rw2[(size_t)EE * DD * FF];
__device__ __half g_actsh_hi[(size_t)TT * FF];
__device__ __half g_actsh_lo[(size_t)TT * FF];
__device__ __half g_actrt_hi[(size_t)EE * CAP * FF];
__device__ __half g_actrt_lo[(size_t)EE * CAP * FF];
__device__ float g_z[(size_t)EE * CAP * DD];
__device__ int   g_counts[EE];
__device__ int   g_tok[EE * CAP];
__device__ float g_gate[EE * CAP];
__device__ int   g_slot[2 * TT];

// ---------------- PTX helpers ----------------
__device__ __forceinline__ uint32_t smem_u32(const void* p) {
    uint32_t a;
    asm("{ .reg .u64 t; cvta.to.shared.u64 t, %1; cvt.u32.u64 %0, t; }" : "=r"(a) : "l"(p));
    return a;
}
#define CPA16(d, s) \
    asm volatile("cp.async.cg.shared.global [%0], [%1], 16;" :: "r"(d), "l"(s) : "memory")
#define CPA_COMMIT() asm volatile("cp.async.commit_group;" ::: "memory")
#define CPA_WAIT1()  asm volatile("cp.async.wait_group 1;" ::: "memory")

#define LDSM4(r0, r1, r2, r3, addr) \
    asm volatile("ldmatrix.sync.aligned.m8n8.x4.shared.b16 {%0,%1,%2,%3}, [%4];" \
                 : "=r"(r0), "=r"(r1), "=r"(r2), "=r"(r3) : "r"(addr))

#define MMA16816(d, a, b0v, b1v) \
    asm volatile("mma.sync.aligned.m16n8k16.row.col.f32.f16.f16.f32 " \
                 "{%0,%1,%2,%3}, {%4,%5,%6,%7}, {%8,%9}, {%0,%1,%2,%3};" \
                 : "+f"((d)[0]), "+f"((d)[1]), "+f"((d)[2]), "+f"((d)[3]) \
                 : "r"((a)[0]), "r"((a)[1]), "r"((a)[2]), "r"((a)[3]), \
                   "r"(b0v), "r"(b1v))

// smem: [tok 512][gate 512][3 stages x 32768 : A 16K | B 16K]
#define STAGE_SZ   32768
#define SM_STAGES  1024
#define SMEM_BYTES (SM_STAGES + 3 * STAGE_SZ)   // 99328

// ---------------- fused fp32 -> fp16 conversion ----------------
struct ConvArgs {
    const float4* src[5];
    __half2*      hi[5];
    __half2*      lo[5];     // null for weights
    int           n4[5];
};

__global__ void conv_kernel(ConvArgs a, int total4)
{
    int i = blockIdx.x * blockDim.x + threadIdx.x;
    if (i >= total4) return;
    int r = 0, j = i;
    while (j >= a.n4[r]) { j -= a.n4[r]; r++; }
    float4 v = a.src[r][j];
    __half h0 = __float2half(v.x), h1 = __float2half(v.y);
    __half h2 = __float2half(v.z), h3 = __float2half(v.w);
    a.hi[r][2 * j]     = __halves2half2(h0, h1);
    a.hi[r][2 * j + 1] = __halves2half2(h2, h3);
    if (a.lo[r]) {
        __half l0 = __float2half(v.x - __half2float(h0));
        __half l1 = __float2half(v.y - __half2float(h1));
        __half l2 = __float2half(v.z - __half2float(h2));
        __half l3 = __float2half(v.w - __half2float(h3));
        a.lo[r][2 * j]     = __halves2half2(l0, l1);
        a.lo[r][2 * j + 1] = __halves2half2(l2, l3);
    }
}

// ---------------- misc kernels ----------------
__global__ void init_kernel() {
    if (threadIdx.x < EE) g_counts[threadIdx.x] = 0;
}

__global__ void router_kernel(const float* __restrict__ x,
                              const float* __restrict__ router)
{
    int warp = (blockIdx.x * blockDim.x + threadIdx.x) >> 5;
    int lane = threadIdx.x & 31;
    if (warp >= TT) return;
    const float* xt = x + (size_t)warp * DD;
    float s[EE];
#pragma unroll
    for (int e = 0; e < EE; e++) s[e] = 0.f;
    for (int d = lane; d < DD; d += 32) {
        float xv = xt[d];
        const float* rr = router + (size_t)d * EE;
#pragma unroll
        for (int e = 0; e < EE; e++) s[e] += xv * rr[e];
    }
#pragma unroll
    for (int e = 0; e < EE; e++)
#pragma unroll
        for (int off = 16; off; off >>= 1)
            s[e] += __shfl_xor_sync(0xffffffffu, s[e], off);
    if (lane == 0) {
        float sc[EE];
#pragma unroll
        for (int e = 0; e < EE; e++) sc[e] = 1.f / (1.f + expf(-s[e]));
        int i1 = 0;
#pragma unroll
        for (int e = 1; e < EE; e++) if (sc[e] > sc[i1]) i1 = e;
        int i2 = (i1 == 0) ? 1 : 0;
#pragma unroll
        for (int e = 0; e < EE; e++)
            if (e != i1 && sc[e] > sc[i2]) i2 = e;
        int p1 = atomicAdd(&g_counts[i1], 1);
        g_tok[i1 * CAP + p1]  = warp;
        g_gate[i1 * CAP + p1] = sc[i1];
        g_slot[2 * warp]      = i1 * CAP + p1;
        int p2 = atomicAdd(&g_counts[i2], 1);
        g_tok[i2 * CAP + p2]  = warp;
        g_gate[i2 * CAP + p2] = sc[i2];
        g_slot[2 * warp + 1]  = i2 * CAP + p2;
    }
}

__global__ void final_add_kernel(float* __restrict__ out)
{
    int t = blockIdx.x;
    size_t s0 = (size_t)g_slot[2 * t];
    size_t s1 = (size_t)g_slot[2 * t + 1];
    float* o = out + (size_t)t * DD;
    const float* z0 = g_z + s0 * DD;
    const float* z1 = g_z + s1 * DD;
    for (int d = threadIdx.x; d < DD; d += blockDim.x)
        o[d] += z0[d] + z1[d];
}

// ---------------- HMMA GEMM: C = A @ B^T over K=2048, fp16x2 compensated ----
// CTA tile 128x128, 4 warps (2x2), warp tile 64x64, BK=64, 3-stage cp.async.
// Two K-phases: A_hi @ B then A_lo @ B into the same fp32 accumulators.
// IS13: B rows interleave w1(even)/w3(odd) -> thread's (d0,d1) = (y0,y1) of one
// act column -> fused gate+SwiGLU, act stored as fp16 hi/lo.
template<bool IS13, bool GATHER>
__global__ void __launch_bounds__(128, 2) moe_gemm(
    const __half* __restrict__ a_hi, const __half* __restrict__ a_lo,
    const __half* __restrict__ b,
    __half* __restrict__ out_hi, __half* __restrict__ out_lo,
    float* __restrict__ out_f,
    int Mfull, const int* __restrict__ counts,
    const int* __restrict__ tok, const float* __restrict__ gate,
    size_t b_estride, int acap, int ccap)
{
    extern __shared__ char smem[];
    const int e   = blockIdx.z;
    const int cnt = counts ? counts[e] : Mfull;
    const int m0  = blockIdx.y * 128;
    if (m0 >= cnt) return;
    const int tid = threadIdx.x;
    const int lane = tid & 31, wid = tid >> 5;

    int*   tok_s  = (int*)smem;
    float* gate_s = (float*)(smem + 512);
    if (GATHER) {
        int r = m0 + tid;
        tok_s[tid]  = (r < cnt) ? tok[e * CAP + r]  : 0;
        gate_s[tid] = (r < cnt) ? gate[e * CAP + r] : 0.f;
    }
    __syncthreads();

    const uint32_t sb = smem_u32(smem) + SM_STAGES;

    // ---- cp.async: each thread owns one 128B row of A and one of B ----
    const int lr = tid;                    // 0..127
    size_t aRow;
    if (GATHER) aRow = (size_t)tok_s[lr];
    else        aRow = (size_t)e * (size_t)acap + (size_t)(m0 + lr);
    const char* pAhi = (const char*)(a_hi + aRow * 2048);
    const char* pAlo = (const char*)(a_lo + aRow * 2048);
    size_t bRow;
    if (IS13) bRow = (size_t)((lr & 1) * 2048 + blockIdx.x * 64 + (lr >> 1));
    else      bRow = (size_t)(blockIdx.x * 128 + lr);
    const char* pB = (const char*)(b + (size_t)e * b_estride + bRow * 2048);

    uint32_t wA[8], wB[8];
#pragma unroll
    for (int j = 0; j < 8; j++) {
        wA[j] = (uint32_t)(lr * 128 + ((j ^ (lr & 7)) << 4));
        wB[j] = (uint32_t)(16384 + lr * 128 + ((j ^ (lr & 7)) << 4));
    }

    // ---- ldmatrix lane addressing (warp tile 64x64) ----
    const int mw = wid >> 1, nw = wid & 1;
    uint32_t abase[4], axor[4], bbase[4], bxor[4];
#pragma unroll
    for (int mi = 0; mi < 4; mi++) {
        int ar = mw * 64 + mi * 16 + (lane & 15);
        abase[mi] = (uint32_t)(ar * 128);
        axor[mi]  = (uint32_t)(ar & 7);
    }
#pragma unroll
    for (int nj = 0; nj < 4; nj++) {
        int br = nw * 64 + nj * 16 + (lane & 15);
        bbase[nj] = (uint32_t)(16384 + br * 128);
        bxor[nj]  = (uint32_t)(br & 7);
    }
    const uint32_t hsel = (uint32_t)(lane >> 4);   // 16B half selector

    float acc[4][8][4];
#pragma unroll
    for (int mi = 0; mi < 4; mi++)
#pragma unroll
        for (int nj = 0; nj < 8; nj++)
#pragma unroll
            for (int q = 0; q < 4; q++) acc[mi][nj][q] = 0.f;

    // iteration c in [0,64): phase = c/32 (A_hi, A_lo), k-chunk 128B = c%32
    auto issue = [&](int c) {
        const uint32_t st = sb + (c % 3) * STAGE_SZ;
        const char* pa = (c < 32) ? pAhi : pAlo;
        const int kb = (c & 31) * 128;
#pragma unroll
        for (int j = 0; j < 8; j++) CPA16(st + wA[j], pa + kb + j * 16);
#pragma unroll
        for (int j = 0; j < 8; j++) CPA16(st + wB[j], pB + kb + j * 16);
        CPA_COMMIT();
    };

    issue(0);
    issue(1);

    for (int c = 0; c < 64; c++) {
        CPA_WAIT1();
        __syncthreads();
        if (c + 2 < 64) issue(c + 2);
        const uint32_t st = sb + (c % 3) * STAGE_SZ;
#pragma unroll
        for (int ks = 0; ks < 4; ks++) {
            uint32_t a[4][4], bf[4][4];
#pragma unroll
            for (int mi = 0; mi < 4; mi++)
                LDSM4(a[mi][0], a[mi][1], a[mi][2], a[mi][3],
                      st + abase[mi] + ((((uint32_t)ks * 2 + hsel) ^ axor[mi]) << 4));
#pragma unroll
            for (int nj = 0; nj < 4; nj++)
                LDSM4(bf[nj][0], bf[nj][1], bf[nj][2], bf[nj][3],
                      st + bbase[nj] + ((((uint32_t)ks * 2 + hsel) ^ bxor[nj]) << 4));
            // x4 B frag: mat0=rows[0:8)c0, mat1=rows[8:16)c0, mat2=rows[0:8)c1, mat3=rows[8:16)c1
#pragma unroll
            for (int mi = 0; mi < 4; mi++)
#pragma unroll
                for (int nj = 0; nj < 4; nj++) {
                    MMA16816(acc[mi][nj * 2],     a[mi], bf[nj][0], bf[nj][2]);
                    MMA16816(acc[mi][nj * 2 + 1], a[mi], bf[nj][1], bf[nj][3]);
                }
        }
    }

    // ---- epilogue ----
    const int t4 = lane & 3;
#pragma unroll
    for (int mi = 0; mi < 4; mi++) {
        const int lr0 = mw * 64 + mi * 16 + (lane >> 2);
        const int lr1 = lr0 + 8;
        const int r0 = m0 + lr0, r1 = m0 + lr1;
        float g0 = 1.f, g1 = 1.f;
        if (IS13 && GATHER) { g0 = gate_s[lr0]; g1 = gate_s[lr1]; }
#pragma unroll
        for (int nj = 0; nj < 8; nj++) {
            if (IS13) {
                const int actcol = blockIdx.x * 64 + nw * 32 + nj * 4 + t4;
                if (r0 < cnt) {
                    float y0 = g0 * acc[mi][nj][0], y1 = g0 * acc[mi][nj][1];
                    float v  = y0 / (1.f + expf(-y0)) * y1;
                    __half h = __float2half(v);
                    size_t o = ((size_t)e * ccap + r0) * 2048 + actcol;
                    out_hi[o] = h;
                    out_lo[o] = __float2half(v - __half2float(h));
                }
                if (r1 < cnt) {
                    float y0 = g1 * acc[mi][nj][2], y1 = g1 * acc[mi][nj][3];
                    float v  = y0 / (1.f + expf(-y0)) * y1;
                    __half h = __float2half(v);
                    size_t o = ((size_t)e * ccap + r1) * 2048 + actcol;
                    out_hi[o] = h;
                    out_lo[o] = __float2half(v - __half2float(h));
                }
            } else {
                const int col = blockIdx.x * 128 + nw * 64 + nj * 8 + t4 * 2;
                if (r0 < cnt)
                    *(float2*)(out_f + ((size_t)e * ccap + r0) * 2048 + col) =
                        make_float2(acc[mi][nj][0], acc[mi][nj][1]);
                if (r1 < cnt)
                    *(float2*)(out_f + ((size_t)e * ccap + r1) * 2048 + col) =
                        make_float2(acc[mi][nj][2], acc[mi][nj][3]);
            }
        }
    }
}

// ---------------- launch ----------------
extern "C" void kernel_launch(void* const* d_in, const int* in_sizes, int n_in,
                              void* d_out, int out_size)
{
    const float* x    = (const float*)d_in[0];
    const float* rte  = (const float*)d_in[1];
    const float* sw13 = (const float*)d_in[2];
    const float* sw2  = (const float*)d_in[3];
    const float* rw13 = (const float*)d_in[4];
    const float* rw2  = (const float*)d_in[5];
    float* out = (float*)d_out;

    __half *xh, *xl, *s13, *s2, *r13, *r2, *ash, *asl, *arh, *arl;
    float *z, *gates;
    int *cnts, *toks;
    cudaGetSymbolAddress((void**)&xh, g_x_hi);
    cudaGetSymbolAddress((void**)&xl, g_x_lo);
    cudaGetSymbolAddress((void**)&s13, g_sw13);
    cudaGetSymbolAddress((void**)&s2, g_sw2);
    cudaGetSymbolAddress((void**)&r13, g_rw13);
    cudaGetSymbolAddress((void**)&r2, g_rw2);
    cudaGetSymbolAddress((void**)&ash, g_actsh_hi);
    cudaGetSymbolAddress((void**)&asl, g_actsh_lo);
    cudaGetSymbolAddress((void**)&arh, g_actrt_hi);
    cudaGetSymbolAddress((void**)&arl, g_actrt_lo);
    cudaGetSymbolAddress((void**)&z, g_z);
    cudaGetSymbolAddress((void**)&cnts, g_counts);
    cudaGetSymbolAddress((void**)&toks, g_tok);
    cudaGetSymbolAddress((void**)&gates, g_gate);

    cudaFuncSetAttribute((const void*)moe_gemm<true,  false>,
                         cudaFuncAttributeMaxDynamicSharedMemorySize, SMEM_BYTES);
    cudaFuncSetAttribute((const void*)moe_gemm<true,  true>,
                         cudaFuncAttributeMaxDynamicSharedMemorySize, SMEM_BYTES);
    cudaFuncSetAttribute((const void*)moe_gemm<false, false>,
                         cudaFuncAttributeMaxDynamicSharedMemorySize, SMEM_BYTES);

    // 1) conversions
    {
        ConvArgs ca;
        ca.src[0] = (const float4*)x;    ca.hi[0] = (__half2*)xh;  ca.lo[0] = (__half2*)xl;
        ca.n4[0]  = TT * DD / 4;
        ca.src[1] = (const float4*)sw13; ca.hi[1] = (__half2*)s13; ca.lo[1] = nullptr;
        ca.n4[1]  = 2 * FF * DD / 4;
        ca.src[2] = (const float4*)sw2;  ca.hi[2] = (__half2*)s2;  ca.lo[2] = nullptr;
        ca.n4[2]  = DD * FF / 4;
        ca.src[3] = (const float4*)rw13; ca.hi[3] = (__half2*)r13; ca.lo[3] = nullptr;
        ca.n4[3]  = EE * 2 * FF * DD / 4;
        ca.src[4] = (const float4*)rw2;  ca.hi[4] = (__half2*)r2;  ca.lo[4] = nullptr;
        ca.n4[4]  = EE * DD * FF / 4;
        int total4 = ca.n4[0] + ca.n4[1] + ca.n4[2] + ca.n4[3] + ca.n4[4];
        conv_kernel<<<(total4 + 255) / 256, 256>>>(ca, total4);
    }

    // 2) init, 3) router
    init_kernel<<<1, 32>>>();
    router_kernel<<<TT / 8, 256>>>(x, rte);

    // 4) shared GEMM13 (fused swiglu -> act_sh)
    moe_gemm<true, false><<<dim3(FF / 64, TT / 128, 1), 128, SMEM_BYTES>>>(
        xh, xl, s13, ash, asl, nullptr,
        TT, nullptr, nullptr, nullptr, 0, TT, TT);

    // 5) routed GEMM13 (gathered + gated -> act_rt)
    moe_gemm<true, true><<<dim3(FF / 64, CAP / 128, EE), 128, SMEM_BYTES>>>(
        xh, xl, r13, arh, arl, nullptr,
        CAP, cnts, toks, gates, (size_t)2 * FF * DD, 0, CAP);

    // 6) shared GEMM2 -> out (fp32, full overwrite)
    moe_gemm<false, false><<<dim3(DD / 128, TT / 128, 1), 128, SMEM_BYTES>>>(
        ash, asl, s2, nullptr, nullptr, out,
        TT, nullptr, nullptr, nullptr, 0, TT, TT);

    // 7) routed GEMM2 -> z
    moe_gemm<false, false><<<dim3(DD / 128, CAP / 128, EE), 128, SMEM_BYTES>>>(
        arh, arl, r2, nullptr, nullptr, z,
        CAP, cnts, nullptr, nullptr, (size_t)DD * FF, CAP, CAP);

    // 8) combine
    final_add_kernel<<<TT, 256>>>(out);
}

// round 7
// speedup vs baseline: 1.6388x; 1.6388x over previous
#include <cuda_runtime.h>
#include <cuda_fp16.h>
#include <cstdint>

#define TT   4096
#define DD   2048
#define FF   2048
#define EE   8
#define CAP  4096

// ---------------- storage: fp16 activations + fp16 weights ----------
__device__ __half g_x16[(size_t)TT * DD];
__device__ __half g_sw13[(size_t)2 * FF * DD];
__device__ __half g_sw2[(size_t)DD * FF];
__device__ __half g_rw13[(size_t)EE * 2 * FF * DD];
__device__ __half g_rw2[(size_t)EE * DD * FF];
__device__ __half g_actsh[(size_t)TT * FF];
__device__ __half g_actrt[(size_t)EE * CAP * FF];
__device__ float g_z[(size_t)EE * CAP * DD];
__device__ int   g_counts[EE];
__device__ int   g_tok[EE * CAP];
__device__ float g_gate[EE * CAP];
__device__ int   g_slot[2 * TT];

// ---------------- PTX helpers ----------------
__device__ __forceinline__ uint32_t smem_u32(const void* p) {
    uint32_t a;
    asm("{ .reg .u64 t; cvta.to.shared.u64 t, %1; cvt.u32.u64 %0, t; }" : "=r"(a) : "l"(p));
    return a;
}
#define CPA16(d, s) \
    asm volatile("cp.async.cg.shared.global [%0], [%1], 16;" :: "r"(d), "l"(s) : "memory")
#define CPA_COMMIT() asm volatile("cp.async.commit_group;" ::: "memory")
#define CPA_WAIT1()  asm volatile("cp.async.wait_group 1;" ::: "memory")

#define LDSM4(r0, r1, r2, r3, addr) \
    asm volatile("ldmatrix.sync.aligned.m8n8.x4.shared.b16 {%0,%1,%2,%3}, [%4];" \
                 : "=r"(r0), "=r"(r1), "=r"(r2), "=r"(r3) : "r"(addr))

#define MMA16816(d, a, b0v, b1v) \
    asm volatile("mma.sync.aligned.m16n8k16.row.col.f32.f16.f16.f32 " \
                 "{%0,%1,%2,%3}, {%4,%5,%6,%7}, {%8,%9}, {%0,%1,%2,%3};" \
                 : "+f"((d)[0]), "+f"((d)[1]), "+f"((d)[2]), "+f"((d)[3]) \
                 : "r"((a)[0]), "r"((a)[1]), "r"((a)[2]), "r"((a)[3]), \
                   "r"(b0v), "r"(b1v))

// smem: [tok 512][gate 512][3 stages x 32768 : A 16K | B 16K]
#define STAGE_SZ   32768
#define SM_STAGES  1024
#define SMEM_BYTES (SM_STAGES + 3 * STAGE_SZ)   // 99328

// ---------------- fused fp32 -> fp16 conversion (5 tensors) ----------------
struct ConvArgs {
    const float4* src[5];
    __half2*      dst[5];
    int           n4[5];
};

__global__ void conv_kernel(ConvArgs a, int total4)
{
    int i = blockIdx.x * blockDim.x + threadIdx.x;
    if (i >= total4) return;
    int r = 0, j = i;
    while (j >= a.n4[r]) { j -= a.n4[r]; r++; }
    float4 v = a.src[r][j];
    a.dst[r][2 * j]     = __halves2half2(__float2half(v.x), __float2half(v.y));
    a.dst[r][2 * j + 1] = __halves2half2(__float2half(v.z), __float2half(v.w));
}

// ---------------- misc kernels ----------------
__global__ void init_kernel() {
    if (threadIdx.x < EE) g_counts[threadIdx.x] = 0;
}

__global__ void router_kernel(const float* __restrict__ x,
                              const float* __restrict__ router)
{
    int warp = (blockIdx.x * blockDim.x + threadIdx.x) >> 5;
    int lane = threadIdx.x & 31;
    if (warp >= TT) return;
    const float* xt = x + (size_t)warp * DD;
    float s[EE];
#pragma unroll
    for (int e = 0; e < EE; e++) s[e] = 0.f;
    for (int d = lane; d < DD; d += 32) {
        float xv = xt[d];
        const float* rr = router + (size_t)d * EE;
#pragma unroll
        for (int e = 0; e < EE; e++) s[e] += xv * rr[e];
    }
#pragma unroll
    for (int e = 0; e < EE; e++)
#pragma unroll
        for (int off = 16; off; off >>= 1)
            s[e] += __shfl_xor_sync(0xffffffffu, s[e], off);
    if (lane == 0) {
        float sc[EE];
#pragma unroll
        for (int e = 0; e < EE; e++) sc[e] = 1.f / (1.f + expf(-s[e]));
        int i1 = 0;
#pragma unroll
        for (int e = 1; e < EE; e++) if (sc[e] > sc[i1]) i1 = e;
        int i2 = (i1 == 0) ? 1 : 0;
#pragma unroll
        for (int e = 0; e < EE; e++)
            if (e != i1 && sc[e] > sc[i2]) i2 = e;
        int p1 = atomicAdd(&g_counts[i1], 1);
        g_tok[i1 * CAP + p1]  = warp;
        g_gate[i1 * CAP + p1] = sc[i1];
        g_slot[2 * warp]      = i1 * CAP + p1;
        int p2 = atomicAdd(&g_counts[i2], 1);
        g_tok[i2 * CAP + p2]  = warp;
        g_gate[i2 * CAP + p2] = sc[i2];
        g_slot[2 * warp + 1]  = i2 * CAP + p2;
    }
}

__global__ void final_add_kernel(float* __restrict__ out)
{
    int t = blockIdx.x;
    size_t s0 = (size_t)g_slot[2 * t];
    size_t s1 = (size_t)g_slot[2 * t + 1];
    float* o = out + (size_t)t * DD;
    const float* z0 = g_z + s0 * DD;
    const float* z1 = g_z + s1 * DD;
    for (int d = threadIdx.x; d < DD; d += blockDim.x)
        o[d] += z0[d] + z1[d];
}

// ---------------- HMMA GEMM: C = A @ B^T over K=2048, fp16 single pass ------
// CTA tile 128x128, 4 warps (2x2), warp tile 64x64, BK=64, 3-stage cp.async.
// IS13: B rows interleave w1(even)/w3(odd) -> thread's (d0,d1) = (y0,y1) of one
// act column -> fused gate+SwiGLU, act stored fp16.
template<bool IS13, bool GATHER>
__global__ void __launch_bounds__(128, 2) moe_gemm(
    const __half* __restrict__ a16,
    const __half* __restrict__ b,
    __half* __restrict__ out_h,
    float* __restrict__ out_f,
    int Mfull, const int* __restrict__ counts,
    const int* __restrict__ tok, const float* __restrict__ gate,
    size_t b_estride, int acap, int ccap)
{
    extern __shared__ char smem[];
    const int e   = blockIdx.z;
    const int cnt = counts ? counts[e] : Mfull;
    const int m0  = blockIdx.y * 128;
    if (m0 >= cnt) return;
    const int tid = threadIdx.x;
    const int lane = tid & 31, wid = tid >> 5;

    int*   tok_s  = (int*)smem;
    float* gate_s = (float*)(smem + 512);
    if (GATHER) {
        int r = m0 + tid;
        tok_s[tid]  = (r < cnt) ? tok[e * CAP + r]  : 0;
        gate_s[tid] = (r < cnt) ? gate[e * CAP + r] : 0.f;
    }
    __syncthreads();

    const uint32_t sb = smem_u32(smem) + SM_STAGES;

    // ---- cp.async: each thread owns one 128B row of A and one of B ----
    const int lr = tid;                    // 0..127
    size_t aRow;
    if (GATHER) aRow = (size_t)tok_s[lr];
    else        aRow = (size_t)e * (size_t)acap + (size_t)(m0 + lr);
    const char* pA = (const char*)(a16 + aRow * 2048);
    size_t bRow;
    if (IS13) bRow = (size_t)((lr & 1) * 2048 + blockIdx.x * 64 + (lr >> 1));
    else      bRow = (size_t)(blockIdx.x * 128 + lr);
    const char* pB = (const char*)(b + (size_t)e * b_estride + bRow * 2048);

    uint32_t wA[8], wB[8];
#pragma unroll
    for (int j = 0; j < 8; j++) {
        wA[j] = (uint32_t)(lr * 128 + ((j ^ (lr & 7)) << 4));
        wB[j] = (uint32_t)(16384 + lr * 128 + ((j ^ (lr & 7)) << 4));
    }

    // ---- ldmatrix lane addressing (warp tile 64x64) ----
    const int mw = wid >> 1, nw = wid & 1;
    uint32_t abase[4], axor[4], bbase[4], bxor[4];
#pragma unroll
    for (int mi = 0; mi < 4; mi++) {
        int ar = mw * 64 + mi * 16 + (lane & 15);
        abase[mi] = (uint32_t)(ar * 128);
        axor[mi]  = (uint32_t)(ar & 7);
    }
#pragma unroll
    for (int nj = 0; nj < 4; nj++) {
        int br = nw * 64 + nj * 16 + (lane & 15);
        bbase[nj] = (uint32_t)(16384 + br * 128);
        bxor[nj]  = (uint32_t)(br & 7);
    }
    const uint32_t hsel = (uint32_t)(lane >> 4);   // 16B half selector

    float acc[4][8][4];
#pragma unroll
    for (int mi = 0; mi < 4; mi++)
#pragma unroll
        for (int nj = 0; nj < 8; nj++)
#pragma unroll
            for (int q = 0; q < 4; q++) acc[mi][nj][q] = 0.f;

    // iteration c in [0,32): k-chunk 128B = c
    auto issue = [&](int c) {
        const uint32_t st = sb + (c % 3) * STAGE_SZ;
        const int kb = c * 128;
#pragma unroll
        for (int j = 0; j < 8; j++) CPA16(st + wA[j], pA + kb + j * 16);
#pragma unroll
        for (int j = 0; j < 8; j++) CPA16(st + wB[j], pB + kb + j * 16);
        CPA_COMMIT();
    };

    issue(0);
    issue(1);

    for (int c = 0; c < 32; c++) {
        CPA_WAIT1();
        __syncthreads();
        if (c + 2 < 32) issue(c + 2);
        const uint32_t st = sb + (c % 3) * STAGE_SZ;
#pragma unroll
        for (int ks = 0; ks < 4; ks++) {
            uint32_t a[4][4], bf[4][4];
#pragma unroll
            for (int mi = 0; mi < 4; mi++)
                LDSM4(a[mi][0], a[mi][1], a[mi][2], a[mi][3],
                      st + abase[mi] + ((((uint32_t)ks * 2 + hsel) ^ axor[mi]) << 4));
#pragma unroll
            for (int nj = 0; nj < 4; nj++)
                LDSM4(bf[nj][0], bf[nj][1], bf[nj][2], bf[nj][3],
                      st + bbase[nj] + ((((uint32_t)ks * 2 + hsel) ^ bxor[nj]) << 4));
#pragma unroll
            for (int mi = 0; mi < 4; mi++)
#pragma unroll
                for (int nj = 0; nj < 4; nj++) {
                    MMA16816(acc[mi][nj * 2],     a[mi], bf[nj][0], bf[nj][2]);
                    MMA16816(acc[mi][nj * 2 + 1], a[mi], bf[nj][1], bf[nj][3]);
                }
        }
    }

    // ---- epilogue ----
    const int t4 = lane & 3;
#pragma unroll
    for (int mi = 0; mi < 4; mi++) {
        const int lr0 = mw * 64 + mi * 16 + (lane >> 2);
        const int lr1 = lr0 + 8;
        const int r0 = m0 + lr0, r1 = m0 + lr1;
        float g0 = 1.f, g1 = 1.f;
        if (IS13 && GATHER) { g0 = gate_s[lr0]; g1 = gate_s[lr1]; }
#pragma unroll
        for (int nj = 0; nj < 8; nj++) {
            if (IS13) {
                const int actcol = blockIdx.x * 64 + nw * 32 + nj * 4 + t4;
                if (r0 < cnt) {
                    float y0 = g0 * acc[mi][nj][0], y1 = g0 * acc[mi][nj][1];
                    float v  = y0 / (1.f + expf(-y0)) * y1;
                    out_h[((size_t)e * ccap + r0) * 2048 + actcol] = __float2half(v);
                }
                if (r1 < cnt) {
                    float y0 = g1 * acc[mi][nj][2], y1 = g1 * acc[mi][nj][3];
                    float v  = y0 / (1.f + expf(-y0)) * y1;
                    out_h[((size_t)e * ccap + r1) * 2048 + actcol] = __float2half(v);
                }
            } else {
                const int col = blockIdx.x * 128 + nw * 64 + nj * 8 + t4 * 2;
                if (r0 < cnt)
                    *(float2*)(out_f + ((size_t)e * ccap + r0) * 2048 + col) =
                        make_float2(acc[mi][nj][0], acc[mi][nj][1]);
                if (r1 < cnt)
                    *(float2*)(out_f + ((size_t)e * ccap + r1) * 2048 + col) =
                        make_float2(acc[mi][nj][2], acc[mi][nj][3]);
            }
        }
    }
}

// ---------------- launch ----------------
extern "C" void kernel_launch(void* const* d_in, const int* in_sizes, int n_in,
                              void* d_out, int out_size)
{
    const float* x    = (const float*)d_in[0];
    const float* rte  = (const float*)d_in[1];
    const float* sw13 = (const float*)d_in[2];
    const float* sw2  = (const float*)d_in[3];
    const float* rw13 = (const float*)d_in[4];
    const float* rw2  = (const float*)d_in[5];
    float* out = (float*)d_out;

    __half *x16, *s13, *s2, *r13, *r2, *ash, *art;
    float *z, *gates;
    int *cnts, *toks;
    cudaGetSymbolAddress((void**)&x16, g_x16);
    cudaGetSymbolAddress((void**)&s13, g_sw13);
    cudaGetSymbolAddress((void**)&s2, g_sw2);
    cudaGetSymbolAddress((void**)&r13, g_rw13);
    cudaGetSymbolAddress((void**)&r2, g_rw2);
    cudaGetSymbolAddress((void**)&ash, g_actsh);
    cudaGetSymbolAddress((void**)&art, g_actrt);
    cudaGetSymbolAddress((void**)&z, g_z);
    cudaGetSymbolAddress((void**)&cnts, g_counts);
    cudaGetSymbolAddress((void**)&toks, g_tok);
    cudaGetSymbolAddress((void**)&gates, g_gate);

    cudaFuncSetAttribute((const void*)moe_gemm<true,  false>,
                         cudaFuncAttributeMaxDynamicSharedMemorySize, SMEM_BYTES);
    cudaFuncSetAttribute((const void*)moe_gemm<true,  true>,
                         cudaFuncAttributeMaxDynamicSharedMemorySize, SMEM_BYTES);
    cudaFuncSetAttribute((const void*)moe_gemm<false, false>,
                         cudaFuncAttributeMaxDynamicSharedMemorySize, SMEM_BYTES);

    // 1) conversions
    {
        ConvArgs ca;
        ca.src[0] = (const float4*)x;    ca.dst[0] = (__half2*)x16;
        ca.n4[0]  = TT * DD / 4;
        ca.src[1] = (const float4*)sw13; ca.dst[1] = (__half2*)s13;
        ca.n4[1]  = 2 * FF * DD / 4;
        ca.src[2] = (const float4*)sw2;  ca.dst[2] = (__half2*)s2;
        ca.n4[2]  = DD * FF / 4;
        ca.src[3] = (const float4*)rw13; ca.dst[3] = (__half2*)r13;
        ca.n4[3]  = EE * 2 * FF * DD / 4;
        ca.src[4] = (const float4*)rw2;  ca.dst[4] = (__half2*)r2;
        ca.n4[4]  = EE * DD * FF / 4;
        int total4 = ca.n4[0] + ca.n4[1] + ca.n4[2] + ca.n4[3] + ca.n4[4];
        conv_kernel<<<(total4 + 255) / 256, 256>>>(ca, total4);
    }

    // 2) init, 3) router
    init_kernel<<<1, 32>>>();
    router_kernel<<<TT / 8, 256>>>(x, rte);

    // 4) shared GEMM13 (fused swiglu -> act_sh)
    moe_gemm<true, false><<<dim3(FF / 64, TT / 128, 1), 128, SMEM_BYTES>>>(
        x16, s13, ash, nullptr,
        TT, nullptr, nullptr, nullptr, 0, TT, TT);

    // 5) routed GEMM13 (gathered + gated -> act_rt)
    moe_gemm<true, true><<<dim3(FF / 64, CAP / 128, EE), 128, SMEM_BYTES>>>(
        x16, r13, art, nullptr,
        CAP, cnts, toks, gates, (size_t)2 * FF * DD, 0, CAP);

    // 6) shared GEMM2 -> out (fp32, full overwrite)
    moe_gemm<false, false><<<dim3(DD / 128, TT / 128, 1), 128, SMEM_BYTES>>>(
        ash, s2, nullptr, out,
        TT, nullptr, nullptr, nullptr, 0, TT, TT);

    // 7) routed GEMM2 -> z
    moe_gemm<false, false><<<dim3(DD / 128, CAP / 128, EE), 128, SMEM_BYTES>>>(
        art, r2, nullptr, z,
        CAP, cnts, nullptr, nullptr, (size_t)DD * FF, CAP, CAP);

    // 8) combine
    final_add_kernel<<<TT, 256>>>(out);
}

// round 11
// speedup vs baseline: 1.8030x; 1.1002x over previous
#include <cuda_runtime.h>
#include <cuda_fp16.h>
#include <cstdint>

#define TT   4096
#define DD   2048
#define FF   2048
#define EE   8
#define CAP  4096

// ---------------- storage: fp16 activations + fp16 weights ----------
__device__ __half g_x16[(size_t)TT * DD];
__device__ __half g_sw13[(size_t)2 * FF * DD];
__device__ __half g_sw2[(size_t)DD * FF];
__device__ __half g_rw13[(size_t)EE * 2 * FF * DD];
__device__ __half g_rw2[(size_t)EE * DD * FF];
__device__ __half g_actsh[(size_t)TT * FF];
__device__ __half g_actrt[(size_t)EE * CAP * FF];
__device__ float g_z[(size_t)EE * CAP * DD];
__device__ int   g_counts[EE];
__device__ int   g_tok[EE * CAP];
__device__ float g_gate[EE * CAP];
__device__ int   g_slot[2 * TT];

// ---------------- PTX helpers ----------------
__device__ __forceinline__ uint32_t smem_u32(const void* p) {
    uint32_t a;
    asm("{ .reg .u64 t; cvta.to.shared.u64 t, %1; cvt.u32.u64 %0, t; }" : "=r"(a) : "l"(p));
    return a;
}
#define CPA16(d, s) \
    asm volatile("cp.async.cg.shared.global [%0], [%1], 16;" :: "r"(d), "l"(s) : "memory")
#define CPA_COMMIT() asm volatile("cp.async.commit_group;" ::: "memory")
#define CPA_WAIT1()  asm volatile("cp.async.wait_group 1;" ::: "memory")

#define LDSM4(r0, r1, r2, r3, addr) \
    asm volatile("ldmatrix.sync.aligned.m8n8.x4.shared.b16 {%0,%1,%2,%3}, [%4];" \
                 : "=r"(r0), "=r"(r1), "=r"(r2), "=r"(r3) : "r"(addr))

#define MMA16816(d, a, b0v, b1v) \
    asm volatile("mma.sync.aligned.m16n8k16.row.col.f32.f16.f16.f32 " \
                 "{%0,%1,%2,%3}, {%4,%5,%6,%7}, {%8,%9}, {%0,%1,%2,%3};" \
                 : "+f"((d)[0]), "+f"((d)[1]), "+f"((d)[2]), "+f"((d)[3]) \
                 : "r"((a)[0]), "r"((a)[1]), "r"((a)[2]), "r"((a)[3]), \
                   "r"(b0v), "r"(b1v))

// smem: [tok 512][gate 512][3 stages x 32768 : A 16K | B 16K]
#define STAGE_SZ   32768
#define SM_STAGES  1024
#define SMEM_BYTES (SM_STAGES + 3 * STAGE_SZ)   // 99328

// ---------------- fp32 -> fp16, 8 floats per iteration ----------------
__device__ __forceinline__ void conv_range(const float4* __restrict__ src,
                                           uint4* __restrict__ dst,
                                           size_t n8, size_t gid, size_t nth)
{
    for (size_t i = gid; i < n8; i += nth) {
        float4 a = __ldcs(src + 2 * i);
        float4 b = __ldcs(src + 2 * i + 1);
        __half2 h0 = __floats2half2_rn(a.x, a.y);
        __half2 h1 = __floats2half2_rn(a.z, a.w);
        __half2 h2 = __floats2half2_rn(b.x, b.y);
        __half2 h3 = __floats2half2_rn(b.z, b.w);
        uint4 o;
        o.x = *reinterpret_cast<uint32_t*>(&h0);
        o.y = *reinterpret_cast<uint32_t*>(&h1);
        o.z = *reinterpret_cast<uint32_t*>(&h2);
        o.w = *reinterpret_cast<uint32_t*>(&h3);
        __stcs(dst + i, o);
    }
}

// standalone: convert x and sw13 (needed before GEMM13s)
__global__ void convA_kernel(const float4* sx, uint4* dx, size_t nx8,
                             const float4* s13, uint4* d13, size_t n13_8)
{
    size_t gid = (size_t)blockIdx.x * blockDim.x + threadIdx.x;
    size_t nth = (size_t)gridDim.x * blockDim.x;
    conv_range(sx, dx, nx8, gid, nth);
    conv_range(s13, d13, n13_8, gid, nth);
}

// ---------------- misc kernels ----------------
__global__ void init_kernel() {
    if (threadIdx.x < EE) g_counts[threadIdx.x] = 0;
}

__global__ void router_kernel(const float* __restrict__ x,
                              const float* __restrict__ router)
{
    int warp = (blockIdx.x * blockDim.x + threadIdx.x) >> 5;
    int lane = threadIdx.x & 31;
    if (warp >= TT) return;
    const float* xt = x + (size_t)warp * DD;
    float s[EE];
#pragma unroll
    for (int e = 0; e < EE; e++) s[e] = 0.f;
    for (int d = lane; d < DD; d += 32) {
        float xv = xt[d];
        const float* rr = router + (size_t)d * EE;
#pragma unroll
        for (int e = 0; e < EE; e++) s[e] += xv * rr[e];
    }
#pragma unroll
    for (int e = 0; e < EE; e++)
#pragma unroll
        for (int off = 16; off; off >>= 1)
            s[e] += __shfl_xor_sync(0xffffffffu, s[e], off);
    if (lane == 0) {
        float sc[EE];
#pragma unroll
        for (int e = 0; e < EE; e++) sc[e] = 1.f / (1.f + expf(-s[e]));
        int i1 = 0;
#pragma unroll
        for (int e = 1; e < EE; e++) if (sc[e] > sc[i1]) i1 = e;
        int i2 = (i1 == 0) ? 1 : 0;
#pragma unroll
        for (int e = 0; e < EE; e++)
            if (e != i1 && sc[e] > sc[i2]) i2 = e;
        int p1 = atomicAdd(&g_counts[i1], 1);
        g_tok[i1 * CAP + p1]  = warp;
        g_gate[i1 * CAP + p1] = sc[i1];
        g_slot[2 * warp]      = i1 * CAP + p1;
        int p2 = atomicAdd(&g_counts[i2], 1);
        g_tok[i2 * CAP + p2]  = warp;
        g_gate[i2 * CAP + p2] = sc[i2];
        g_slot[2 * warp + 1]  = i2 * CAP + p2;
    }
}

__global__ void final_add_kernel(float* __restrict__ out)
{
    int t = blockIdx.x;
    size_t s0 = (size_t)g_slot[2 * t];
    size_t s1 = (size_t)g_slot[2 * t + 1];
    float* o = out + (size_t)t * DD;
    const float* z0 = g_z + s0 * DD;
    const float* z1 = g_z + s1 * DD;
    for (int d = threadIdx.x; d < DD; d += blockDim.x)
        o[d] += z0[d] + z1[d];
}

// ---------------- HMMA GEMM: C = A @ B^T over K=2048, fp16 single pass ------
// CTA tile 128x128, 4 warps (2x2), warp tile 64x64, BK=64, 3-stage cp.async.
// IS13: B rows interleave w1(even)/w3(odd) -> thread's (d0,d1) = (y0,y1) of one
// act column -> fused gate+SwiGLU, act stored fp16.
// convz >= 0: blocks with blockIdx.z == convz instead convert cv0/cv1 fp32->fp16
// (weight tensors needed only by a LATER kernel -> hidden behind this GEMM).
template<bool IS13, bool GATHER>
__global__ void __launch_bounds__(128, 2) moe_gemm(
    const __half* __restrict__ a16,
    const __half* __restrict__ b,
    __half* __restrict__ out_h,
    float* __restrict__ out_f,
    int Mfull, const int* __restrict__ counts,
    const int* __restrict__ tok, const float* __restrict__ gate,
    size_t b_estride, int acap, int ccap,
    int convz,
    const float4* __restrict__ cv_s0, uint4* __restrict__ cv_d0, size_t cv_n0,
    const float4* __restrict__ cv_s1, uint4* __restrict__ cv_d1, size_t cv_n1)
{
    extern __shared__ char smem[];
    const int tid = threadIdx.x;

    if (convz >= 0 && blockIdx.z == (unsigned)convz) {
        size_t gid = ((size_t)blockIdx.y * gridDim.x + blockIdx.x) * blockDim.x + tid;
        size_t nth = (size_t)gridDim.x * gridDim.y * blockDim.x;
        if (cv_n0) conv_range(cv_s0, cv_d0, cv_n0, gid, nth);
        if (cv_n1) conv_range(cv_s1, cv_d1, cv_n1, gid, nth);
        return;
    }

    const int e   = blockIdx.z;
    const int cnt = counts ? counts[e] : Mfull;
    const int m0  = blockIdx.y * 128;
    if (m0 >= cnt) return;
    const int lane = tid & 31, wid = tid >> 5;

    int*   tok_s  = (int*)smem;
    float* gate_s = (float*)(smem + 512);
    if (GATHER) {
        int r = m0 + tid;
        tok_s[tid]  = (r < cnt) ? tok[e * CAP + r]  : 0;
        gate_s[tid] = (r < cnt) ? gate[e * CAP + r] : 0.f;
    }
    __syncthreads();

    const uint32_t sb = smem_u32(smem) + SM_STAGES;

    // ---- cp.async: each thread owns one 128B row of A and one of B ----
    const int lr = tid;                    // 0..127
    size_t aRow;
    if (GATHER) aRow = (size_t)tok_s[lr];
    else        aRow = (size_t)e * (size_t)acap + (size_t)(m0 + lr);
    const char* pA = (const char*)(a16 + aRow * 2048);
    size_t bRow;
    if (IS13) bRow = (size_t)((lr & 1) * 2048 + blockIdx.x * 64 + (lr >> 1));
    else      bRow = (size_t)(blockIdx.x * 128 + lr);
    const char* pB = (const char*)(b + (size_t)e * b_estride + bRow * 2048);

    uint32_t wA[8], wB[8];
#pragma unroll
    for (int j = 0; j < 8; j++) {
        wA[j] = (uint32_t)(lr * 128 + ((j ^ (lr & 7)) << 4));
        wB[j] = (uint32_t)(16384 + lr * 128 + ((j ^ (lr & 7)) << 4));
    }

    // ---- ldmatrix lane addressing (warp tile 64x64) ----
    const int mw = wid >> 1, nw = wid & 1;
    uint32_t abase[4], axor[4], bbase[4], bxor[4];
#pragma unroll
    for (int mi = 0; mi < 4; mi++) {
        int ar = mw * 64 + mi * 16 + (lane & 15);
        abase[mi] = (uint32_t)(ar * 128);
        axor[mi]  = (uint32_t)(ar & 7);
    }
#pragma unroll
    for (int nj = 0; nj < 4; nj++) {
        int br = nw * 64 + nj * 16 + (lane & 15);
        bbase[nj] = (uint32_t)(16384 + br * 128);
        bxor[nj]  = (uint32_t)(br & 7);
    }
    const uint32_t hsel = (uint32_t)(lane >> 4);   // 16B half selector

    float acc[4][8][4];
#pragma unroll
    for (int mi = 0; mi < 4; mi++)
#pragma unroll
        for (int nj = 0; nj < 8; nj++)
#pragma unroll
            for (int q = 0; q < 4; q++) acc[mi][nj][q] = 0.f;

    // iteration c in [0,32): k-chunk 128B = c
    auto issue = [&](int c) {
        const uint32_t st = sb + (c % 3) * STAGE_SZ;
        const int kb = c * 128;
#pragma unroll
        for (int j = 0; j < 8; j++) CPA16(st + wA[j], pA + kb + j * 16);
#pragma unroll
        for (int j = 0; j < 8; j++) CPA16(st + wB[j], pB + kb + j * 16);
        CPA_COMMIT();
    };

    issue(0);
    issue(1);

    for (int c = 0; c < 32; c++) {
        CPA_WAIT1();
        __syncthreads();
        if (c + 2 < 32) issue(c + 2);
        const uint32_t st = sb + (c % 3) * STAGE_SZ;
#pragma unroll
        for (int ks = 0; ks < 4; ks++) {
            uint32_t a[4][4], bf[4][4];
#pragma unroll
            for (int mi = 0; mi < 4; mi++)
                LDSM4(a[mi][0], a[mi][1], a[mi][2], a[mi][3],
                      st + abase[mi] + ((((uint32_t)ks * 2 + hsel) ^ axor[mi]) << 4));
#pragma unroll
            for (int nj = 0; nj < 4; nj++)
                LDSM4(bf[nj][0], bf[nj][1], bf[nj][2], bf[nj][3],
                      st + bbase[nj] + ((((uint32_t)ks * 2 + hsel) ^ bxor[nj]) << 4));
#pragma unroll
            for (int mi = 0; mi < 4; mi++)
#pragma unroll
                for (int nj = 0; nj < 4; nj++) {
                    MMA16816(acc[mi][nj * 2],     a[mi], bf[nj][0], bf[nj][2]);
                    MMA16816(acc[mi][nj * 2 + 1], a[mi], bf[nj][1], bf[nj][3]);
                }
        }
    }

    // ---- epilogue ----
    const int t4 = lane & 3;
#pragma unroll
    for (int mi = 0; mi < 4; mi++) {
        const int lr0 = mw * 64 + mi * 16 + (lane >> 2);
        const int lr1 = lr0 + 8;
        const int r0 = m0 + lr0, r1 = m0 + lr1;
        float g0 = 1.f, g1 = 1.f;
        if (IS13 && GATHER) { g0 = gate_s[lr0]; g1 = gate_s[lr1]; }
#pragma unroll
        for (int nj = 0; nj < 8; nj++) {
            if (IS13) {
                const int actcol = blockIdx.x * 64 + nw * 32 + nj * 4 + t4;
                if (r0 < cnt) {
                    float y0 = g0 * acc[mi][nj][0], y1 = g0 * acc[mi][nj][1];
                    float v  = y0 / (1.f + expf(-y0)) * y1;
                    out_h[((size_t)e * ccap + r0) * 2048 + actcol] = __float2half(v);
                }
                if (r1 < cnt) {
                    float y0 = g1 * acc[mi][nj][2], y1 = g1 * acc[mi][nj][3];
                    float v  = y0 / (1.f + expf(-y0)) * y1;
                    out_h[((size_t)e * ccap + r1) * 2048 + actcol] = __float2half(v);
                }
            } else {
                const int col = blockIdx.x * 128 + nw * 64 + nj * 8 + t4 * 2;
                if (r0 < cnt)
                    *(float2*)(out_f + ((size_t)e * ccap + r0) * 2048 + col) =
                        make_float2(acc[mi][nj][0], acc[mi][nj][1]);
                if (r1 < cnt)
                    *(float2*)(out_f + ((size_t)e * ccap + r1) * 2048 + col) =
                        make_float2(acc[mi][nj][2], acc[mi][nj][3]);
            }
        }
    }
}

// ---------------- launch ----------------
extern "C" void kernel_launch(void* const* d_in, const int* in_sizes, int n_in,
                              void* d_out, int out_size)
{
    const float* x    = (const float*)d_in[0];
    const float* rte  = (const float*)d_in[1];
    const float* sw13 = (const float*)d_in[2];
    const float* sw2  = (const float*)d_in[3];
    const float* rw13 = (const float*)d_in[4];
    const float* rw2  = (const float*)d_in[5];
    float* out = (float*)d_out;

    __half *x16, *s13, *s2, *r13, *r2, *ash, *art;
    float *z, *gates;
    int *cnts, *toks;
    cudaGetSymbolAddress((void**)&x16, g_x16);
    cudaGetSymbolAddress((void**)&s13, g_sw13);
    cudaGetSymbolAddress((void**)&s2, g_sw2);
    cudaGetSymbolAddress((void**)&r13, g_rw13);
    cudaGetSymbolAddress((void**)&r2, g_rw2);
    cudaGetSymbolAddress((void**)&ash, g_actsh);
    cudaGetSymbolAddress((void**)&art, g_actrt);
    cudaGetSymbolAddress((void**)&z, g_z);
    cudaGetSymbolAddress((void**)&cnts, g_counts);
    cudaGetSymbolAddress((void**)&toks, g_tok);
    cudaGetSymbolAddress((void**)&gates, g_gate);

    cudaFuncSetAttribute((const void*)moe_gemm<true,  false>,
                         cudaFuncAttributeMaxDynamicSharedMemorySize, SMEM_BYTES);
    cudaFuncSetAttribute((const void*)moe_gemm<true,  true>,
                         cudaFuncAttributeMaxDynamicSharedMemorySize, SMEM_BYTES);
    cudaFuncSetAttribute((const void*)moe_gemm<false, false>,
                         cudaFuncAttributeMaxDynamicSharedMemorySize, SMEM_BYTES);

    // 1) init + router + convert x/sw13 (only what GEMM13 needs up front)
    init_kernel<<<1, 32>>>();
    router_kernel<<<TT / 8, 256>>>(x, rte);
    convA_kernel<<<1024, 256>>>((const float4*)x, (uint4*)x16, (size_t)TT * DD / 8,
                                (const float4*)sw13, (uint4*)s13,
                                (size_t)2 * FF * DD / 8);

    // 2) shared GEMM13 (fused swiglu -> act_sh) + hidden rw13 conversion
    moe_gemm<true, false><<<dim3(FF / 64, TT / 128, 2), 128, SMEM_BYTES>>>(
        x16, s13, ash, nullptr,
        TT, nullptr, nullptr, nullptr, 0, TT, TT,
        /*convz=*/1,
        (const float4*)rw13, (uint4*)r13, (size_t)EE * 2 * FF * DD / 8,
        nullptr, nullptr, 0);

    // 3) routed GEMM13 (gathered + gated -> act_rt) + hidden sw2/rw2 conversion
    moe_gemm<true, true><<<dim3(FF / 64, CAP / 128, EE + 1), 128, SMEM_BYTES>>>(
        x16, r13, art, nullptr,
        CAP, cnts, toks, gates, (size_t)2 * FF * DD, 0, CAP,
        /*convz=*/EE,
        (const float4*)sw2, (uint4*)s2, (size_t)DD * FF / 8,
        (const float4*)rw2, (uint4*)r2, (size_t)EE * DD * FF / 8);

    // 4) shared GEMM2 -> out (fp32, full overwrite)
    moe_gemm<false, false><<<dim3(DD / 128, TT / 128, 1), 128, SMEM_BYTES>>>(
        ash, s2, nullptr, out,
        TT, nullptr, nullptr, nullptr, 0, TT, TT,
        -1, nullptr, nullptr, 0, nullptr, nullptr, 0);

    // 5) routed GEMM2 -> z
    moe_gemm<false, false><<<dim3(DD / 128, CAP / 128, EE), 128, SMEM_BYTES>>>(
        art, r2, nullptr, z,
        CAP, cnts, nullptr, nullptr, (size_t)DD * FF, CAP, CAP,
        -1, nullptr, nullptr, 0, nullptr, nullptr, 0);

    // 6) combine
    final_add_kernel<<<TT, 256>>>(out);
}

// round 14
// speedup vs baseline: 1.8302x; 1.0151x over previous
#include <cuda_runtime.h>
#include <cuda_fp16.h>
#include <cstdint>

#define TT   4096
#define DD   2048
#define FF   2048
#define EE   8
#define CAP  4096

// ---------------- storage: fp16 activations + fp16 weights ----------
__device__ __half g_x16[(size_t)TT * DD];
__device__ __half g_sw13[(size_t)2 * FF * DD];
__device__ __half g_sw2[(size_t)DD * FF];
__device__ __half g_rw13[(size_t)EE * 2 * FF * DD];
__device__ __half g_rw2[(size_t)EE * DD * FF];
__device__ __half g_actsh[(size_t)TT * FF];
__device__ __half g_actrt[(size_t)EE * CAP * FF];
__device__ int   g_counts[EE];
__device__ int   g_tok[EE * CAP];
__device__ float g_gate[EE * CAP];

// ---------------- PTX helpers ----------------
__device__ __forceinline__ uint32_t smem_u32(const void* p) {
    uint32_t a;
    asm("{ .reg .u64 t; cvta.to.shared.u64 t, %1; cvt.u32.u64 %0, t; }" : "=r"(a) : "l"(p));
    return a;
}
#define CPA16(d, s) \
    asm volatile("cp.async.cg.shared.global [%0], [%1], 16;" :: "r"(d), "l"(s) : "memory")
#define CPA_COMMIT() asm volatile("cp.async.commit_group;" ::: "memory")
#define CPA_WAIT1()  asm volatile("cp.async.wait_group 1;" ::: "memory")

#define LDSM4(r0, r1, r2, r3, addr) \
    asm volatile("ldmatrix.sync.aligned.m8n8.x4.shared.b16 {%0,%1,%2,%3}, [%4];" \
                 : "=r"(r0), "=r"(r1), "=r"(r2), "=r"(r3) : "r"(addr))

#define MMA16816(d, a, b0v, b1v) \
    asm volatile("mma.sync.aligned.m16n8k16.row.col.f32.f16.f16.f32 " \
                 "{%0,%1,%2,%3}, {%4,%5,%6,%7}, {%8,%9}, {%0,%1,%2,%3};" \
                 : "+f"((d)[0]), "+f"((d)[1]), "+f"((d)[2]), "+f"((d)[3]) \
                 : "r"((a)[0]), "r"((a)[1]), "r"((a)[2]), "r"((a)[3]), \
                   "r"(b0v), "r"(b1v))

// smem: [tok 512][gate 512][3 stages x 32768 : A 16K | B 16K]
#define STAGE_SZ   32768
#define SM_STAGES  1024
#define SMEM_BYTES (SM_STAGES + 3 * STAGE_SZ)   // 99328

// ---------------- fp32 -> fp16, 8 floats per iteration ----------------
__device__ __forceinline__ void conv_range(const float4* __restrict__ src,
                                           uint4* __restrict__ dst,
                                           size_t n8, size_t gid, size_t nth)
{
    for (size_t i = gid; i < n8; i += nth) {
        float4 a = __ldcs(src + 2 * i);
        float4 b = __ldcs(src + 2 * i + 1);
        __half2 h0 = __floats2half2_rn(a.x, a.y);
        __half2 h1 = __floats2half2_rn(a.z, a.w);
        __half2 h2 = __floats2half2_rn(b.x, b.y);
        __half2 h3 = __floats2half2_rn(b.z, b.w);
        uint4 o;
        o.x = *reinterpret_cast<uint32_t*>(&h0);
        o.y = *reinterpret_cast<uint32_t*>(&h1);
        o.z = *reinterpret_cast<uint32_t*>(&h2);
        o.w = *reinterpret_cast<uint32_t*>(&h3);
        __stcs(dst + i, o);
    }
}

// ---------------- zero out + counters ----------------
__global__ void zero_kernel(float4* __restrict__ out, int n4)
{
    int i = blockIdx.x * blockDim.x + threadIdx.x;
    if (i < n4) out[i] = make_float4(0.f, 0.f, 0.f, 0.f);
    if (blockIdx.x == 0 && threadIdx.x < EE) g_counts[threadIdx.x] = 0;
}

// ---------------- prep: conv x/sw13 (blocks <1024) + router (blocks >=1024) --
__global__ void prep_kernel(const float* __restrict__ x,
                            const float* __restrict__ router,
                            uint4* __restrict__ dx, uint4* __restrict__ d13)
{
    if (blockIdx.x < 1024) {
        size_t gid = (size_t)blockIdx.x * blockDim.x + threadIdx.x;
        size_t nth = (size_t)1024 * blockDim.x;
        conv_range((const float4*)x, dx, (size_t)TT * DD / 8, gid, nth);
        conv_range((const float4*)(x == nullptr ? nullptr : x), d13, 0, gid, nth); // placeholder
        return;
    }
    int warp = (int)(((blockIdx.x - 1024) * blockDim.x + threadIdx.x) >> 5);
    int lane = threadIdx.x & 31;
    if (warp >= TT) return;
    const float* xt = x + (size_t)warp * DD;
    float s[EE];
#pragma unroll
    for (int e = 0; e < EE; e++) s[e] = 0.f;
    for (int d = lane; d < DD; d += 32) {
        float xv = xt[d];
        const float* rr = router + (size_t)d * EE;
#pragma unroll
        for (int e = 0; e < EE; e++) s[e] += xv * rr[e];
    }
#pragma unroll
    for (int e = 0; e < EE; e++)
#pragma unroll
        for (int off = 16; off; off >>= 1)
            s[e] += __shfl_xor_sync(0xffffffffu, s[e], off);
    if (lane == 0) {
        float sc[EE];
#pragma unroll
        for (int e = 0; e < EE; e++) sc[e] = 1.f / (1.f + expf(-s[e]));
        int i1 = 0;
#pragma unroll
        for (int e = 1; e < EE; e++) if (sc[e] > sc[i1]) i1 = e;
        int i2 = (i1 == 0) ? 1 : 0;
#pragma unroll
        for (int e = 0; e < EE; e++)
            if (e != i1 && sc[e] > sc[i2]) i2 = e;
        int p1 = atomicAdd(&g_counts[i1], 1);
        g_tok[i1 * CAP + p1]  = warp;
        g_gate[i1 * CAP + p1] = sc[i1];
        int p2 = atomicAdd(&g_counts[i2], 1);
        g_tok[i2 * CAP + p2]  = warp;
        g_gate[i2 * CAP + p2] = sc[i2];
    }
}

// standalone sw13 conversion folded into prep via second kernel arg is clunky;
// do it here: sw13 conversion runs in the SAME prep launch via blocks <1024.
__global__ void conv13_kernel(const float4* s13, uint4* d13, size_t n8)
{
    size_t gid = (size_t)blockIdx.x * blockDim.x + threadIdx.x;
    size_t nth = (size_t)gridDim.x * blockDim.x;
    conv_range(s13, d13, n8, gid, nth);
}

// ---------------- GEMM13: act = swiglu(gate * (A @ W13^T)) -------------------
// CTA tile 128x128, 4 warps (2x2), warp tile 64x64, BK=64, 3-stage cp.async.
// B rows interleave w1(even)/w3(odd). convz slice converts weights for later.
template<bool GATHER>
__global__ void __launch_bounds__(128, 2) moe_gemm13(
    const __half* __restrict__ a16,
    const __half* __restrict__ b,
    __half* __restrict__ out_h,
    int Mfull, const int* __restrict__ counts,
    const int* __restrict__ tok, const float* __restrict__ gate,
    size_t b_estride, int ccap,
    int convz,
    const float4* __restrict__ cv_s0, uint4* __restrict__ cv_d0, size_t cv_n0,
    const float4* __restrict__ cv_s1, uint4* __restrict__ cv_d1, size_t cv_n1)
{
    extern __shared__ char smem[];
    const int tid = threadIdx.x;

    if (convz >= 0 && blockIdx.z == (unsigned)convz) {
        size_t gid = ((size_t)blockIdx.y * gridDim.x + blockIdx.x) * blockDim.x + tid;
        size_t nth = (size_t)gridDim.x * gridDim.y * blockDim.x;
        if (cv_n0) conv_range(cv_s0, cv_d0, cv_n0, gid, nth);
        if (cv_n1) conv_range(cv_s1, cv_d1, cv_n1, gid, nth);
        return;
    }

    const int e   = blockIdx.z;
    const int cnt = counts ? counts[e] : Mfull;
    const int m0  = blockIdx.y * 128;
    if (m0 >= cnt) return;
    const int lane = tid & 31, wid = tid >> 5;

    int*   tok_s  = (int*)smem;
    float* gate_s = (float*)(smem + 512);
    if (GATHER) {
        int r = m0 + tid;
        tok_s[tid]  = (r < cnt) ? tok[e * CAP + r]  : 0;
        gate_s[tid] = (r < cnt) ? gate[e * CAP + r] : 0.f;
    }
    __syncthreads();

    const uint32_t sb = smem_u32(smem) + SM_STAGES;

    const int lr = tid;
    size_t aRow;
    if (GATHER) aRow = (size_t)tok_s[lr];
    else        aRow = (size_t)(m0 + lr);
    const char* pA = (const char*)(a16 + aRow * 2048);
    size_t bRow = (size_t)((lr & 1) * 2048 + blockIdx.x * 64 + (lr >> 1));
    const char* pB = (const char*)(b + (size_t)e * b_estride + bRow * 2048);

    uint32_t wA[8], wB[8];
#pragma unroll
    for (int j = 0; j < 8; j++) {
        wA[j] = (uint32_t)(lr * 128 + ((j ^ (lr & 7)) << 4));
        wB[j] = (uint32_t)(16384 + lr * 128 + ((j ^ (lr & 7)) << 4));
    }

    const int mw = wid >> 1, nw = wid & 1;
    uint32_t abase[4], axor[4], bbase[4], bxor[4];
#pragma unroll
    for (int mi = 0; mi < 4; mi++) {
        int ar = mw * 64 + mi * 16 + (lane & 15);
        abase[mi] = (uint32_t)(ar * 128);
        axor[mi]  = (uint32_t)(ar & 7);
    }
#pragma unroll
    for (int nj = 0; nj < 4; nj++) {
        int br = nw * 64 + nj * 16 + (lane & 15);
        bbase[nj] = (uint32_t)(16384 + br * 128);
        bxor[nj]  = (uint32_t)(br & 7);
    }
    const uint32_t hsel = (uint32_t)(lane >> 4);

    float acc[4][8][4];
#pragma unroll
    for (int mi = 0; mi < 4; mi++)
#pragma unroll
        for (int nj = 0; nj < 8; nj++)
#pragma unroll
            for (int q = 0; q < 4; q++) acc[mi][nj][q] = 0.f;

    auto issue = [&](int c) {
        const uint32_t st = sb + (c % 3) * STAGE_SZ;
        const int kb = c * 128;
#pragma unroll
        for (int j = 0; j < 8; j++) CPA16(st + wA[j], pA + kb + j * 16);
#pragma unroll
        for (int j = 0; j < 8; j++) CPA16(st + wB[j], pB + kb + j * 16);
        CPA_COMMIT();
    };

    issue(0);
    issue(1);

    for (int c = 0; c < 32; c++) {
        CPA_WAIT1();
        __syncthreads();
        if (c + 2 < 32) issue(c + 2);
        const uint32_t st = sb + (c % 3) * STAGE_SZ;
#pragma unroll
        for (int ks = 0; ks < 4; ks++) {
            uint32_t a[4][4], bf[4][4];
#pragma unroll
            for (int mi = 0; mi < 4; mi++)
                LDSM4(a[mi][0], a[mi][1], a[mi][2], a[mi][3],
                      st + abase[mi] + ((((uint32_t)ks * 2 + hsel) ^ axor[mi]) << 4));
#pragma unroll
            for (int nj = 0; nj < 4; nj++)
                LDSM4(bf[nj][0], bf[nj][1], bf[nj][2], bf[nj][3],
                      st + bbase[nj] + ((((uint32_t)ks * 2 + hsel) ^ bxor[nj]) << 4));
#pragma unroll
            for (int mi = 0; mi < 4; mi++)
#pragma unroll
                for (int nj = 0; nj < 4; nj++) {
                    MMA16816(acc[mi][nj * 2],     a[mi], bf[nj][0], bf[nj][2]);
                    MMA16816(acc[mi][nj * 2 + 1], a[mi], bf[nj][1], bf[nj][3]);
                }
        }
    }

    const int t4 = lane & 3;
#pragma unroll
    for (int mi = 0; mi < 4; mi++) {
        const int lr0 = mw * 64 + mi * 16 + (lane >> 2);
        const int lr1 = lr0 + 8;
        const int r0 = m0 + lr0, r1 = m0 + lr1;
        float g0 = 1.f, g1 = 1.f;
        if (GATHER) { g0 = gate_s[lr0]; g1 = gate_s[lr1]; }
#pragma unroll
        for (int nj = 0; nj < 8; nj++) {
            const int actcol = blockIdx.x * 64 + nw * 32 + nj * 4 + t4;
            if (r0 < cnt) {
                float y0 = g0 * acc[mi][nj][0], y1 = g0 * acc[mi][nj][1];
                float v  = y0 / (1.f + expf(-y0)) * y1;
                out_h[((size_t)e * ccap + r0) * 2048 + actcol] = __float2half(v);
            }
            if (r1 < cnt) {
                float y0 = g1 * acc[mi][nj][2], y1 = g1 * acc[mi][nj][3];
                float v  = y0 / (1.f + expf(-y0)) * y1;
                out_h[((size_t)e * ccap + r1) * 2048 + actcol] = __float2half(v);
            }
        }
    }
}

// ---------------- GEMM2 merged: out += act @ W2^T (atomicAdd epilogue) -------
// z in [0, 8]: z<8 routed expert (A = actrt slot rows, scatter rows via tok),
// z==8 shared (A = actsh, identity rows).
__global__ void __launch_bounds__(128, 2) moe_gemm2(
    const __half* __restrict__ actrt, const __half* __restrict__ actsh,
    const __half* __restrict__ rw2,  const __half* __restrict__ sw2,
    float* __restrict__ out,
    const int* __restrict__ counts, const int* __restrict__ tok)
{
    extern __shared__ char smem[];
    const int tid = threadIdx.x;
    const int e   = blockIdx.z;
    const bool shared_e = (e == EE);
    const int cnt = shared_e ? TT : counts[e];
    const int m0  = blockIdx.y * 128;
    if (m0 >= cnt) return;
    const int lane = tid & 31, wid = tid >> 5;

    int* tok_s = (int*)smem;
    {
        int r = m0 + tid;
        tok_s[tid] = shared_e ? r : ((r < cnt) ? tok[e * CAP + r] : 0);
    }
    __syncthreads();

    const uint32_t sb = smem_u32(smem) + SM_STAGES;

    const int lr = tid;
    const char* pA = shared_e
        ? (const char*)(actsh + (size_t)(m0 + lr) * 2048)
        : (const char*)(actrt + ((size_t)e * CAP + (m0 + lr)) * 2048);
    size_t bRow = (size_t)(blockIdx.x * 128 + lr);
    const char* pB = shared_e
        ? (const char*)(sw2 + bRow * 2048)
        : (const char*)(rw2 + (size_t)e * DD * FF + bRow * 2048);

    uint32_t wA[8], wB[8];
#pragma unroll
    for (int j = 0; j < 8; j++) {
        wA[j] = (uint32_t)(lr * 128 + ((j ^ (lr & 7)) << 4));
        wB[j] = (uint32_t)(16384 + lr * 128 + ((j ^ (lr & 7)) << 4));
    }

    const int mw = wid >> 1, nw = wid & 1;
    uint32_t abase[4], axor[4], bbase[4], bxor[4];
#pragma unroll
    for (int mi = 0; mi < 4; mi++) {
        int ar = mw * 64 + mi * 16 + (lane & 15);
        abase[mi] = (uint32_t)(ar * 128);
        axor[mi]  = (uint32_t)(ar & 7);
    }
#pragma unroll
    for (int nj = 0; nj < 4; nj++) {
        int br = nw * 64 + nj * 16 + (lane & 15);
        bbase[nj] = (uint32_t)(16384 + br * 128);
        bxor[nj]  = (uint32_t)(br & 7);
    }
    const uint32_t hsel = (uint32_t)(lane >> 4);

    float acc[4][8][4];
#pragma unroll
    for (int mi = 0; mi < 4; mi++)
#pragma unroll
        for (int nj = 0; nj < 8; nj++)
#pragma unroll
            for (int q = 0; q < 4; q++) acc[mi][nj][q] = 0.f;

    auto issue = [&](int c) {
        const uint32_t st = sb + (c % 3) * STAGE_SZ;
        const int kb = c * 128;
#pragma unroll
        for (int j = 0; j < 8; j++) CPA16(st + wA[j], pA + kb + j * 16);
#pragma unroll
        for (int j = 0; j < 8; j++) CPA16(st + wB[j], pB + kb + j * 16);
        CPA_COMMIT();
    };

    issue(0);
    issue(1);

    for (int c = 0; c < 32; c++) {
        CPA_WAIT1();
        __syncthreads();
        if (c + 2 < 32) issue(c + 2);
        const uint32_t st = sb + (c % 3) * STAGE_SZ;
#pragma unroll
        for (int ks = 0; ks < 4; ks++) {
            uint32_t a[4][4], bf[4][4];
#pragma unroll
            for (int mi = 0; mi < 4; mi++)
                LDSM4(a[mi][0], a[mi][1], a[mi][2], a[mi][3],
                      st + abase[mi] + ((((uint32_t)ks * 2 + hsel) ^ axor[mi]) << 4));
#pragma unroll
            for (int nj = 0; nj < 4; nj++)
                LDSM4(bf[nj][0], bf[nj][1], bf[nj][2], bf[nj][3],
                      st + bbase[nj] + ((((uint32_t)ks * 2 + hsel) ^ bxor[nj]) << 4));
#pragma unroll
            for (int mi = 0; mi < 4; mi++)
#pragma unroll
                for (int nj = 0; nj < 4; nj++) {
                    MMA16816(acc[mi][nj * 2],     a[mi], bf[nj][0], bf[nj][2]);
                    MMA16816(acc[mi][nj * 2 + 1], a[mi], bf[nj][1], bf[nj][3]);
                }
        }
    }

    const int t4 = lane & 3;
#pragma unroll
    for (int mi = 0; mi < 4; mi++) {
        const int lr0 = mw * 64 + mi * 16 + (lane >> 2);
        const int lr1 = lr0 + 8;
        const int r0 = m0 + lr0, r1 = m0 + lr1;
        const int to0 = tok_s[lr0], to1 = tok_s[lr1];
#pragma unroll
        for (int nj = 0; nj < 8; nj++) {
            const int col = blockIdx.x * 128 + nw * 64 + nj * 8 + t4 * 2;
            if (r0 < cnt) {
                float* p = out + (size_t)to0 * 2048 + col;
                atomicAdd(p,     acc[mi][nj][0]);
                atomicAdd(p + 1, acc[mi][nj][1]);
            }
            if (r1 < cnt) {
                float* p = out + (size_t)to1 * 2048 + col;
                atomicAdd(p,     acc[mi][nj][2]);
                atomicAdd(p + 1, acc[mi][nj][3]);
            }
        }
    }
}

// ---------------- launch ----------------
extern "C" void kernel_launch(void* const* d_in, const int* in_sizes, int n_in,
                              void* d_out, int out_size)
{
    const float* x    = (const float*)d_in[0];
    const float* rte  = (const float*)d_in[1];
    const float* sw13 = (const float*)d_in[2];
    const float* sw2  = (const float*)d_in[3];
    const float* rw13 = (const float*)d_in[4];
    const float* rw2  = (const float*)d_in[5];
    float* out = (float*)d_out;

    __half *x16, *s13, *s2, *r13, *r2, *ash, *art;
    float *gates;
    int *cnts, *toks;
    cudaGetSymbolAddress((void**)&x16, g_x16);
    cudaGetSymbolAddress((void**)&s13, g_sw13);
    cudaGetSymbolAddress((void**)&s2, g_sw2);
    cudaGetSymbolAddress((void**)&r13, g_rw13);
    cudaGetSymbolAddress((void**)&r2, g_rw2);
    cudaGetSymbolAddress((void**)&ash, g_actsh);
    cudaGetSymbolAddress((void**)&art, g_actrt);
    cudaGetSymbolAddress((void**)&cnts, g_counts);
    cudaGetSymbolAddress((void**)&toks, g_tok);
    cudaGetSymbolAddress((void**)&gates, g_gate);

    cudaFuncSetAttribute((const void*)moe_gemm13<false>,
                         cudaFuncAttributeMaxDynamicSharedMemorySize, SMEM_BYTES);
    cudaFuncSetAttribute((const void*)moe_gemm13<true>,
                         cudaFuncAttributeMaxDynamicSharedMemorySize, SMEM_BYTES);
    cudaFuncSetAttribute((const void*)moe_gemm2,
                         cudaFuncAttributeMaxDynamicSharedMemorySize, SMEM_BYTES);

    // 1) zero out + counters
    zero_kernel<<<(TT * DD / 4 + 255) / 256, 256>>>((float4*)out, TT * DD / 4);

    // 2) conv x (+ router merged)  and  conv sw13
    prep_kernel<<<1024 + 512, 256>>>(x, rte, (uint4*)x16, nullptr);
    conv13_kernel<<<512, 256>>>((const float4*)sw13, (uint4*)s13,
                                (size_t)2 * FF * DD / 8);

    // 3) shared GEMM13 (fused swiglu -> actsh) + hidden rw13 conversion
    moe_gemm13<false><<<dim3(FF / 64, TT / 128, 2), 128, SMEM_BYTES>>>(
        x16, s13, ash,
        TT, nullptr, nullptr, nullptr, 0, TT,
        /*convz=*/1,
        (const float4*)rw13, (uint4*)r13, (size_t)EE * 2 * FF * DD / 8,
        nullptr, nullptr, 0);

    // 4) routed GEMM13 (gathered + gated -> actrt) + hidden sw2/rw2 conversion
    moe_gemm13<true><<<dim3(FF / 64, CAP / 128, EE + 1), 128, SMEM_BYTES>>>(
        x16, r13, art,
        CAP, cnts, toks, gates, (size_t)2 * FF * DD, CAP,
        /*convz=*/EE,
        (const float4*)sw2, (uint4*)s2, (size_t)DD * FF / 8,
        (const float4*)rw2, (uint4*)r2, (size_t)EE * DD * FF / 8);

    // 5) merged GEMM2 (shared + routed, atomicAdd into zeroed out)
    moe_gemm2<<<dim3(DD / 128, TT / 128, EE + 1), 128, SMEM_BYTES>>>(
        art, ash, r2, s2, out, cnts, toks);
}